// round 3
// baseline (speedup 1.0000x reference)
#include <cuda_runtime.h>
#include <cstdint>

#define NN 100000
#define EE 1600000
#define DD 128
#define DEE 16
#define GG 512
#define BN_EPS 1e-5f

// ---------------- scratch (device globals; no allocation) ----------------
__device__ __align__(16) float g_xw[NN * DD];    // xw * dinv[row] (layer 1 and 2, reused)
__device__ __align__(16) float g_acc[NN * DD];   // scatter accumulator (zeroed per layer)
__device__ __align__(16) float g_h[NN * DD];     // post BN+ReLU hidden (layer1 output)
__device__ float g_deg[NN];
__device__ float g_dinv[NN];
__device__ int   g_src32[EE];
__device__ int   g_dst32[EE];
__device__ int   g_egr[EE];        // graph id per edge = batch[src]
__device__ int   g_eperm[EE];      // edge ids bucketed by graph
__device__ int   g_nb32[NN];       // batch id per node (int32)
__device__ int   g_ecnt[GG];
__device__ int   g_gcnt[GG];
__device__ int   g_eoff[GG + 1];
__device__ int   g_ecur[GG];
__device__ __align__(16) float g_gsum[GG * DD];
__device__ __align__(16) float g_esum[GG * DD];
__device__ int   g_is64;           // 1 if integer inputs are int64, 0 if int32

__device__ __forceinline__ void red_add_v4(float* addr, float4 v) {
    asm volatile("red.global.add.v4.f32 [%0], {%1, %2, %3, %4};"
                 :: "l"(__cvta_generic_to_global(addr)),
                    "f"(v.x), "f"(v.y), "f"(v.z), "f"(v.w)
                 : "memory");
}

__device__ __forceinline__ int clampi(int v, int lo, int hi) {
    return min(max(v, lo), hi);
}

// ---------------- dtype probe: int64 iff all odd 32-bit words are zero ----------------
__global__ void k_detect(const int* __restrict__ ei_raw) {
    __shared__ int nz;
    if (threadIdx.x == 0) nz = 0;
    __syncthreads();
    for (int i = threadIdx.x; i < 1024; i += blockDim.x) {
        if (ei_raw[2 * i + 1] != 0) nz = 1;   // benign race; any write -> 1
    }
    __syncthreads();
    if (threadIdx.x == 0) g_is64 = (nz == 0) ? 1 : 0;
}

// ---------------- init ----------------
__global__ void k_init() {
    int i = blockIdx.x * blockDim.x + threadIdx.x;
    int stride = gridDim.x * blockDim.x;  // 262144 > GG*DD, NN
    for (int idx = i; idx < NN * DD; idx += stride) {
        g_acc[idx] = 0.f;
        if (idx < GG * DD) { g_gsum[idx] = 0.f; g_esum[idx] = 0.f; }
        if (idx < NN) g_deg[idx] = 1.0f;          // self-loop
        if (idx < GG) { g_ecnt[idx] = 0; g_gcnt[idx] = 0; }
    }
}

// ---------------- edge prep: int32 indices, degree, edge-graph histogram ----------------
__global__ void k_edge_prep(const void* __restrict__ ei_raw,
                            const void* __restrict__ batch_raw) {
    __shared__ int hist[GG];
    for (int t = threadIdx.x; t < GG; t += blockDim.x) hist[t] = 0;
    __syncthreads();
    const int is64 = g_is64;
    const int*       ei32 = (const int*)ei_raw;
    const long long* ei64 = (const long long*)ei_raw;
    const int*       bt32 = (const int*)batch_raw;
    const long long* bt64 = (const long long*)batch_raw;
    int i0 = blockIdx.x * blockDim.x + threadIdx.x;
    int stride = gridDim.x * blockDim.x;
    for (int e = i0; e < EE; e += stride) {
        int s, d;
        if (is64) { s = (int)ei64[e]; d = (int)ei64[EE + e]; }
        else      { s = ei32[e];      d = ei32[EE + e]; }
        s = clampi(s, 0, NN - 1);
        d = clampi(d, 0, NN - 1);
        g_src32[e] = s;
        g_dst32[e] = d;
        atomicAdd(&g_deg[d], 1.0f);
        int gr = is64 ? (int)bt64[s] : bt32[s];
        gr = clampi(gr, 0, GG - 1);
        g_egr[e] = gr;
        atomicAdd(&hist[gr], 1);
    }
    __syncthreads();
    for (int t = threadIdx.x; t < GG; t += blockDim.x)
        if (hist[t]) atomicAdd(&g_ecnt[t], hist[t]);
}

// ---------------- node prep: batch int32 + per-graph node counts ----------------
__global__ void k_node_prep(const void* __restrict__ batch_raw) {
    __shared__ int hist[GG];
    for (int t = threadIdx.x; t < GG; t += blockDim.x) hist[t] = 0;
    __syncthreads();
    const int is64 = g_is64;
    const int*       bt32 = (const int*)batch_raw;
    const long long* bt64 = (const long long*)batch_raw;
    int i0 = blockIdx.x * blockDim.x + threadIdx.x;
    int stride = gridDim.x * blockDim.x;
    for (int v = i0; v < NN; v += stride) {
        int gr = is64 ? (int)bt64[v] : bt32[v];
        gr = clampi(gr, 0, GG - 1);
        g_nb32[v] = gr;
        atomicAdd(&hist[gr], 1);
    }
    __syncthreads();
    for (int t = threadIdx.x; t < GG; t += blockDim.x)
        if (hist[t]) atomicAdd(&g_gcnt[t], hist[t]);
}

__global__ void k_dinv() {
    int i = blockIdx.x * blockDim.x + threadIdx.x;
    if (i < NN) g_dinv[i] = rsqrtf(g_deg[i]);   // deg >= 1 always (self-loop)
}

// ---------------- exclusive scan of edge-per-graph counts (512, single block) ----------------
__global__ void k_scan() {
    __shared__ int s[GG];
    int t = threadIdx.x;
    int v = g_ecnt[t];
    s[t] = v;
    __syncthreads();
    for (int off = 1; off < GG; off <<= 1) {
        int add = (t >= off) ? s[t - off] : 0;
        __syncthreads();
        s[t] += add;
        __syncthreads();
    }
    int excl = s[t] - v;
    g_eoff[t] = excl;
    g_ecur[t] = excl;
    if (t == GG - 1) g_eoff[GG] = s[t];
}

// ---------------- bucket edges by graph ----------------
__global__ void k_escatter() {
    int i0 = blockIdx.x * blockDim.x + threadIdx.x;
    int stride = gridDim.x * blockDim.x;
    for (int e = i0; e < EE; e += stride) {
        int gr = g_egr[e];
        int p = atomicAdd(&g_ecur[gr], 1);
        if (p < EE) g_eperm[p] = e;
    }
}

// ---------------- GEMM: out = (X @ W) * dinv[row], 64x128 tile, fp32 FFMA ----------------
__global__ void __launch_bounds__(256) k_gemm_scale(const float* __restrict__ X,
                                                    const float* __restrict__ W,
                                                    int layer) {
    const float* __restrict__ Xp = (layer == 2) ? (const float*)g_h : X;
    __shared__ __align__(16) float Xs[64 * 16];
    __shared__ __align__(16) float Ws[16 * 128];
    int tid = threadIdx.x;
    int tx = tid & 31, ty = tid >> 5;
    int r0 = blockIdx.x * 64;
    float acc[8][4];
#pragma unroll
    for (int i = 0; i < 8; i++)
#pragma unroll
        for (int j = 0; j < 4; j++) acc[i][j] = 0.f;

    for (int k0 = 0; k0 < 128; k0 += 16) {
        {   // stage X tile [64 x 16]
            int i0 = tid * 4;
            int row = i0 >> 4, kk = i0 & 15;
            int gr = r0 + row;
            float4 v = make_float4(0.f, 0.f, 0.f, 0.f);
            if (gr < NN) v = *(const float4*)&Xp[gr * 128 + k0 + kk];
            *(float4*)&Xs[row * 16 + kk] = v;
        }
        {   // stage W tile [16 x 128]
            int i0 = tid * 8;
            int r = i0 >> 7, c = i0 & 127;
            *(float4*)&Ws[r * 128 + c]     = *(const float4*)&W[(k0 + r) * 128 + c];
            *(float4*)&Ws[r * 128 + c + 4] = *(const float4*)&W[(k0 + r) * 128 + c + 4];
        }
        __syncthreads();
#pragma unroll
        for (int kk = 0; kk < 16; kk++) {
            float4 b = *(float4*)&Ws[kk * 128 + 4 * tx];
#pragma unroll
            for (int i = 0; i < 8; i++) {
                float a = Xs[(8 * ty + i) * 16 + kk];
                acc[i][0] = fmaf(a, b.x, acc[i][0]);
                acc[i][1] = fmaf(a, b.y, acc[i][1]);
                acc[i][2] = fmaf(a, b.z, acc[i][2]);
                acc[i][3] = fmaf(a, b.w, acc[i][3]);
            }
        }
        __syncthreads();
    }
#pragma unroll
    for (int i = 0; i < 8; i++) {
        int row = r0 + 8 * ty + i;
        if (row < NN) {
            float s = g_dinv[row];
            float4 o = make_float4(acc[i][0] * s, acc[i][1] * s, acc[i][2] * s, acc[i][3] * s);
            *(float4*)&g_xw[row * 128 + 4 * tx] = o;
        }
    }
}

// ---------------- edge scatter-aggregation: acc[dst] += xw_scaled[src] ----------------
__global__ void k_agg() {
    int gtid = blockIdx.x * blockDim.x + threadIdx.x;
    int warp = gtid >> 5;
    int lane = threadIdx.x & 31;
    int nw = (gridDim.x * blockDim.x) >> 5;
    // EE % 4 == 0, e0 multiple of 4 -> all 4 valid when e0 < EE
    for (int e0 = warp * 4; e0 < EE; e0 += nw * 4) {
        int s[4], d[4];
#pragma unroll
        for (int u = 0; u < 4; u++) {
            s[u] = __ldg(&g_src32[e0 + u]);
            d[u] = __ldg(&g_dst32[e0 + u]);
        }
        float4 v[4];
#pragma unroll
        for (int u = 0; u < 4; u++)
            v[u] = *(const float4*)&g_xw[s[u] * 128 + 4 * lane];
#pragma unroll
        for (int u = 0; u < 4; u++)
            red_add_v4(&g_acc[d[u] * 128 + 4 * lane], v[u]);
    }
}

// ---------------- epilogue layer1: h = relu(bn(dinv*(acc+xw) + b)); re-zero acc ----------------
__global__ void k_epi1(const float* __restrict__ b, const float* __restrict__ gam,
                       const float* __restrict__ bet, const float* __restrict__ mu,
                       const float* __restrict__ var) {
    int i0 = blockIdx.x * blockDim.x + threadIdx.x;
    int stride = gridDim.x * blockDim.x;
    for (int idx = i0; idx < NN * DD; idx += stride) {
        int dd = idx & 127;
        int v = idx >> 7;
        float val = g_dinv[v] * (g_acc[idx] + g_xw[idx]) + __ldg(&b[dd]);
        float sc = __ldg(&gam[dd]) * rsqrtf(__ldg(&var[dd]) + BN_EPS);
        val = (val - __ldg(&mu[dd])) * sc + __ldg(&bet[dd]);
        g_h[idx] = fmaxf(val, 0.f);
        g_acc[idx] = 0.f;   // ready for layer 2
    }
}

// ---------------- epilogue layer2 + mean-pool scatter ----------------
__global__ void k_epi2_pool(const float* __restrict__ b, const float* __restrict__ gam,
                            const float* __restrict__ bet, const float* __restrict__ mu,
                            const float* __restrict__ var) {
    int gtid = blockIdx.x * blockDim.x + threadIdx.x;
    int warp = gtid >> 5;
    int lane = threadIdx.x & 31;
    int nw = (gridDim.x * blockDim.x) >> 5;
    int dd = 4 * lane;
    float b0 = __ldg(&b[dd]),   b1v = __ldg(&b[dd+1]), b2v = __ldg(&b[dd+2]), b3v = __ldg(&b[dd+3]);
    float g0 = __ldg(&gam[dd]), g1v = __ldg(&gam[dd+1]), g2v = __ldg(&gam[dd+2]), g3v = __ldg(&gam[dd+3]);
    float t0 = __ldg(&bet[dd]), t1 = __ldg(&bet[dd+1]), t2 = __ldg(&bet[dd+2]), t3 = __ldg(&bet[dd+3]);
    float m0 = __ldg(&mu[dd]),  m1v = __ldg(&mu[dd+1]), m2v = __ldg(&mu[dd+2]), m3v = __ldg(&mu[dd+3]);
    float v0 = __ldg(&var[dd]), v1v = __ldg(&var[dd+1]), v2v = __ldg(&var[dd+2]), v3v = __ldg(&var[dd+3]);
    float s0 = g0  * rsqrtf(v0  + BN_EPS);
    float s1 = g1v * rsqrtf(v1v + BN_EPS);
    float s2 = g2v * rsqrtf(v2v + BN_EPS);
    float s3 = g3v * rsqrtf(v3v + BN_EPS);
    float c0 = (b0  - m0 ) * s0 + t0;
    float c1 = (b1v - m1v) * s1 + t1;
    float c2 = (b2v - m2v) * s2 + t2;
    float c3 = (b3v - m3v) * s3 + t3;
    for (int v = warp; v < NN; v += nw) {
        int idx = v * 128 + dd;
        float4 a = *(const float4*)&g_acc[idx];
        float4 x = *(const float4*)&g_xw[idx];
        float din = g_dinv[v];
        float4 r;
        r.x = fmaxf(din * (a.x + x.x) * s0 + c0, 0.f);
        r.y = fmaxf(din * (a.y + x.y) * s1 + c1, 0.f);
        r.z = fmaxf(din * (a.z + x.z) * s2 + c2, 0.f);
        r.w = fmaxf(din * (a.w + x.w) * s3 + c3, 0.f);
        int gr = g_nb32[v];
        red_add_v4(&g_gsum[gr * 128 + dd], r);
    }
}

// ---------------- edge encoder: per-graph register-accumulated relu(ea@We1+be1) ----------------
#define ECHUNKS 3
__global__ void __launch_bounds__(128) k_edge_enc(const float* __restrict__ EA,
                                                  const float* __restrict__ We1,
                                                  const float* __restrict__ be1) {
    int g = blockIdx.x;
    int lo = g_eoff[g], hi = g_eoff[g + 1];
    int cnt = hi - lo;
    int y = blockIdx.y;
    int cl = lo + (int)((long long)cnt * y / ECHUNKS);
    int ch = lo + (int)((long long)cnt * (y + 1) / ECHUNKS);
    int lane = threadIdx.x & 31;
    int w = threadIdx.x >> 5;

    float wr0[16], wr1[16], wr2[16], wr3[16];
#pragma unroll
    for (int k = 0; k < 16; k++) {
        wr0[k] = __ldg(&We1[k * 128 + lane]);
        wr1[k] = __ldg(&We1[k * 128 + 32 + lane]);
        wr2[k] = __ldg(&We1[k * 128 + 64 + lane]);
        wr3[k] = __ldg(&We1[k * 128 + 96 + lane]);
    }
    float br0 = __ldg(&be1[lane]);
    float br1 = __ldg(&be1[32 + lane]);
    float br2 = __ldg(&be1[64 + lane]);
    float br3 = __ldg(&be1[96 + lane]);
    float a0 = 0.f, a1 = 0.f, a2 = 0.f, a3 = 0.f;

    __shared__ __align__(16) float4 s_ea[128 * 4];   // 128 edges x 16 floats
    for (int base = cl; base < ch; base += 128) {
        int n = min(128, ch - base);
        if ((int)threadIdx.x < n) {
            int e = g_eperm[base + threadIdx.x];
            const float4* p = (const float4*)&EA[(long long)e * 16];
            s_ea[threadIdx.x * 4 + 0] = __ldg(&p[0]);
            s_ea[threadIdx.x * 4 + 1] = __ldg(&p[1]);
            s_ea[threadIdx.x * 4 + 2] = __ldg(&p[2]);
            s_ea[threadIdx.x * 4 + 3] = __ldg(&p[3]);
        }
        __syncthreads();
        for (int j = w; j < n; j += 4) {
            float o0 = br0, o1 = br1, o2 = br2, o3 = br3;
#pragma unroll
            for (int q = 0; q < 4; q++) {
                float4 A = s_ea[j * 4 + q];
                float av[4] = {A.x, A.y, A.z, A.w};
#pragma unroll
                for (int kk = 0; kk < 4; kk++) {
                    int k = q * 4 + kk;
                    float aa = av[kk];
                    o0 = fmaf(aa, wr0[k], o0);
                    o1 = fmaf(aa, wr1[k], o1);
                    o2 = fmaf(aa, wr2[k], o2);
                    o3 = fmaf(aa, wr3[k], o3);
                }
            }
            a0 += fmaxf(o0, 0.f);
            a1 += fmaxf(o1, 0.f);
            a2 += fmaxf(o2, 0.f);
            a3 += fmaxf(o3, 0.f);
        }
        __syncthreads();
    }
    __shared__ float s_red[4][128];
    s_red[w][lane] = a0;
    s_red[w][32 + lane] = a1;
    s_red[w][64 + lane] = a2;
    s_red[w][96 + lane] = a3;
    __syncthreads();
    int t = threadIdx.x;
    float tot = s_red[0][t] + s_red[1][t] + s_red[2][t] + s_red[3][t];
    atomicAdd(&g_esum[g * 128 + t], tot);
}

// ---------------- final: out = gsum/cnt + mask*(mean_he @ We2 + be2) ----------------
__global__ void k_final(const float* __restrict__ We2, const float* __restrict__ be2,
                        float* __restrict__ out) {
    int g = blockIdx.x;
    int t = threadIdx.x;
    __shared__ float mh[128];
    int ec = g_ecnt[g];
    float inv = 1.0f / (float)max(ec, 1);
    mh[t] = g_esum[g * 128 + t] * inv;
    __syncthreads();
    float er = 0.f;
    if (ec > 0) {
#pragma unroll 8
        for (int k = 0; k < 128; k++)
            er = fmaf(mh[k], __ldg(&We2[k * 128 + t]), er);
        er += __ldg(&be2[t]);
    }
    float nc = (float)g_gcnt[g];
    float grp = g_gsum[g * 128 + t] / fmaxf(nc, 1.0f);
    out[g * 128 + t] = grp + er;
}

// ---------------- launch ----------------
extern "C" void kernel_launch(void* const* d_in, const int* in_sizes, int n_in,
                              void* d_out, int out_size) {
    const float* x     = (const float*)d_in[0];
    const void*  ei    = d_in[1];
    const void*  batch = d_in[2];
    const float* ea    = (const float*)d_in[3];
    // 16 weight tensors always trail; num_graphs may or may not be a device input.
    int base = n_in - 16;
    const float* W1  = (const float*)d_in[base + 0];
    const float* b1  = (const float*)d_in[base + 1];
    const float* g1  = (const float*)d_in[base + 2];
    const float* bt1 = (const float*)d_in[base + 3];
    const float* m1  = (const float*)d_in[base + 4];
    const float* v1  = (const float*)d_in[base + 5];
    const float* W2  = (const float*)d_in[base + 6];
    const float* b2  = (const float*)d_in[base + 7];
    const float* g2  = (const float*)d_in[base + 8];
    const float* bt2 = (const float*)d_in[base + 9];
    const float* m2  = (const float*)d_in[base + 10];
    const float* v2  = (const float*)d_in[base + 11];
    const float* We1 = (const float*)d_in[base + 12];
    const float* be1 = (const float*)d_in[base + 13];
    const float* We2 = (const float*)d_in[base + 14];
    const float* be2 = (const float*)d_in[base + 15];
    float* out = (float*)d_out;

    k_detect<<<1, 256>>>((const int*)ei);
    k_init<<<1024, 256>>>();
    k_edge_prep<<<2048, 256>>>(ei, batch);
    k_node_prep<<<512, 256>>>(batch);
    k_dinv<<<(NN + 255) / 256, 256>>>();
    k_scan<<<1, GG>>>();
    k_escatter<<<2048, 256>>>();

    // layer 1
    k_gemm_scale<<<(NN + 63) / 64, 256>>>(x, W1, 1);
    k_agg<<<1184, 256>>>();
    k_epi1<<<8192, 256>>>(b1, g1, bt1, m1, v1);

    // layer 2 (+ fused pooling)
    k_gemm_scale<<<(NN + 63) / 64, 256>>>(x, W2, 2);
    k_agg<<<1184, 256>>>();
    k_epi2_pool<<<1563, 256>>>(b2, g2, bt2, m2, v2);

    // edge encoder (bucketed by graph, register accumulation)
    {
        dim3 grid(GG, ECHUNKS);
        k_edge_enc<<<grid, 128>>>(ea, We1, be1);
    }

    k_final<<<GG, 128>>>(We2, be2, out);
}

// round 4
// speedup vs baseline: 1.1094x; 1.1094x over previous
#include <cuda_runtime.h>
#include <cstdint>

#define NN 100000
#define EE 1600000
#define DD 128
#define DEE 16
#define GG 512
#define BN_EPS 1e-5f

// ---------------- scratch (device globals; no allocation) ----------------
__device__ __align__(16) float g_xw[NN * DD];    // (X@W) * dinv[row], per layer
__device__ __align__(16) float g_h[NN * DD];     // layer1 output (post BN+ReLU)
__device__ float g_dinv[NN];
__device__ int   g_degi[NN];       // in-degree (edges only)
__device__ int   g_doff[NN + 1];   // CSR offsets by dst
__device__ int   g_dcur[NN];
__device__ int   g_src32[EE];
__device__ int   g_dst32[EE];
__device__ int   g_ssorted[EE];    // src ids sorted by dst
__device__ int   g_egr[EE];        // graph id per edge = batch[src]
__device__ int   g_eperm[EE];      // edge ids bucketed by graph
__device__ int   g_nb32[NN];       // batch id per node
__device__ int   g_ecnt[GG];
__device__ int   g_gcnt[GG];
__device__ int   g_eoff[GG + 1];
__device__ int   g_ecur[GG];
__device__ __align__(16) float g_gsum[GG * DD];
__device__ __align__(16) float g_esum[GG * DD];
__device__ int   g_is64;

__device__ __forceinline__ void red_add_v4(float* addr, float4 v) {
    asm volatile("red.global.add.v4.f32 [%0], {%1, %2, %3, %4};"
                 :: "l"(__cvta_generic_to_global(addr)),
                    "f"(v.x), "f"(v.y), "f"(v.z), "f"(v.w)
                 : "memory");
}
__device__ __forceinline__ int clampi(int v, int lo, int hi) {
    return min(max(v, lo), hi);
}

// ---------------- dtype probe ----------------
__global__ void k_detect(const int* __restrict__ ei_raw) {
    __shared__ int nz;
    if (threadIdx.x == 0) nz = 0;
    __syncthreads();
    for (int i = threadIdx.x; i < 1024; i += blockDim.x)
        if (ei_raw[2 * i + 1] != 0) nz = 1;
    __syncthreads();
    if (threadIdx.x == 0) g_is64 = (nz == 0) ? 1 : 0;
}

// ---------------- init (small buffers only) ----------------
__global__ void k_init() {
    int i = blockIdx.x * blockDim.x + threadIdx.x;
    int stride = gridDim.x * blockDim.x;
    for (int idx = i; idx < NN; idx += stride) {
        g_degi[idx] = 0;
        if (idx < GG * DD) { g_gsum[idx] = 0.f; g_esum[idx] = 0.f; }
        if (idx < GG) { g_ecnt[idx] = 0; g_gcnt[idx] = 0; }
    }
}

// ---------------- edge prep ----------------
__global__ void k_edge_prep(const void* __restrict__ ei_raw,
                            const void* __restrict__ batch_raw) {
    __shared__ int hist[GG];
    for (int t = threadIdx.x; t < GG; t += blockDim.x) hist[t] = 0;
    __syncthreads();
    const int is64 = g_is64;
    const int*       ei32 = (const int*)ei_raw;
    const long long* ei64 = (const long long*)ei_raw;
    const int*       bt32 = (const int*)batch_raw;
    const long long* bt64 = (const long long*)batch_raw;
    int i0 = blockIdx.x * blockDim.x + threadIdx.x;
    int stride = gridDim.x * blockDim.x;
    for (int e = i0; e < EE; e += stride) {
        int s, d;
        if (is64) { s = (int)ei64[e]; d = (int)ei64[EE + e]; }
        else      { s = ei32[e];      d = ei32[EE + e]; }
        s = clampi(s, 0, NN - 1);
        d = clampi(d, 0, NN - 1);
        g_src32[e] = s;
        g_dst32[e] = d;
        atomicAdd(&g_degi[d], 1);
        int gr = is64 ? (int)bt64[s] : bt32[s];
        gr = clampi(gr, 0, GG - 1);
        g_egr[e] = gr;
        atomicAdd(&hist[gr], 1);
    }
    __syncthreads();
    for (int t = threadIdx.x; t < GG; t += blockDim.x)
        if (hist[t]) atomicAdd(&g_ecnt[t], hist[t]);
}

// ---------------- node prep ----------------
__global__ void k_node_prep(const void* __restrict__ batch_raw) {
    __shared__ int hist[GG];
    for (int t = threadIdx.x; t < GG; t += blockDim.x) hist[t] = 0;
    __syncthreads();
    const int is64 = g_is64;
    const int*       bt32 = (const int*)batch_raw;
    const long long* bt64 = (const long long*)batch_raw;
    int i0 = blockIdx.x * blockDim.x + threadIdx.x;
    int stride = gridDim.x * blockDim.x;
    for (int v = i0; v < NN; v += stride) {
        int gr = is64 ? (int)bt64[v] : bt32[v];
        gr = clampi(gr, 0, GG - 1);
        g_nb32[v] = gr;
        atomicAdd(&hist[gr], 1);
    }
    __syncthreads();
    for (int t = threadIdx.x; t < GG; t += blockDim.x)
        if (hist[t]) atomicAdd(&g_gcnt[t], hist[t]);
}

__global__ void k_dinv() {
    int i = blockIdx.x * blockDim.x + threadIdx.x;
    if (i < NN) g_dinv[i] = rsqrtf((float)(g_degi[i] + 1));
}

// ---------------- per-graph edge scan (512, one block) ----------------
__global__ void k_scan_graph() {
    __shared__ int s[GG];
    int t = threadIdx.x;
    int v = g_ecnt[t];
    s[t] = v;
    __syncthreads();
    for (int off = 1; off < GG; off <<= 1) {
        int add = (t >= off) ? s[t - off] : 0;
        __syncthreads();
        s[t] += add;
        __syncthreads();
    }
    int excl = s[t] - v;
    g_eoff[t] = excl;
    g_ecur[t] = excl;
    if (t == GG - 1) g_eoff[GG] = s[t];
}

// ---------------- CSR-by-dst scan (100000, one block of 1024) ----------------
#define SCH 98   // 1024 * 98 = 100352 >= NN
__global__ void k_scan_nodes() {
    __shared__ int part[1024];
    int t = threadIdx.x;
    int base = t * SCH;
    int sum = 0;
    for (int i = 0; i < SCH; i++) {
        int idx = base + i;
        if (idx < NN) sum += g_degi[idx];
    }
    part[t] = sum;
    __syncthreads();
    for (int off = 1; off < 1024; off <<= 1) {
        int add = (t >= off) ? part[t - off] : 0;
        __syncthreads();
        part[t] += add;
        __syncthreads();
    }
    int run = part[t] - sum;   // exclusive prefix of this chunk
    for (int i = 0; i < SCH; i++) {
        int idx = base + i;
        if (idx < NN) {
            g_doff[idx] = run;
            g_dcur[idx] = run;
            run += g_degi[idx];
        }
    }
    if (t == 1023) g_doff[NN] = EE;
}

// ---------------- scatter: bucket by graph (encoder) + sort by dst (agg) ----------------
__global__ void k_escatter() {
    int i0 = blockIdx.x * blockDim.x + threadIdx.x;
    int stride = gridDim.x * blockDim.x;
    for (int e = i0; e < EE; e += stride) {
        int gr = g_egr[e];
        int p = atomicAdd(&g_ecur[gr], 1);
        if (p < EE) g_eperm[p] = e;
        int d = g_dst32[e];
        int q = atomicAdd(&g_dcur[d], 1);
        if (q < EE) g_ssorted[q] = g_src32[e];
    }
}

// ---------------- GEMM: g_xw = (X @ W) * dinv[row], 64x128 tile ----------------
__global__ void __launch_bounds__(256) k_gemm_scale(const float* __restrict__ X,
                                                    const float* __restrict__ W,
                                                    int layer) {
    const float* __restrict__ Xp = (layer == 2) ? (const float*)g_h : X;
    __shared__ __align__(16) float Xs[64 * 16];
    __shared__ __align__(16) float Ws[16 * 128];
    int tid = threadIdx.x;
    int tx = tid & 31, ty = tid >> 5;
    int r0 = blockIdx.x * 64;
    float acc[8][4];
#pragma unroll
    for (int i = 0; i < 8; i++)
#pragma unroll
        for (int j = 0; j < 4; j++) acc[i][j] = 0.f;

    for (int k0 = 0; k0 < 128; k0 += 16) {
        {
            int i0 = tid * 4;
            int row = i0 >> 4, kk = i0 & 15;
            int gr = r0 + row;
            float4 v = make_float4(0.f, 0.f, 0.f, 0.f);
            if (gr < NN) v = *(const float4*)&Xp[gr * 128 + k0 + kk];
            *(float4*)&Xs[row * 16 + kk] = v;
        }
        {
            int i0 = tid * 8;
            int r = i0 >> 7, c = i0 & 127;
            *(float4*)&Ws[r * 128 + c]     = *(const float4*)&W[(k0 + r) * 128 + c];
            *(float4*)&Ws[r * 128 + c + 4] = *(const float4*)&W[(k0 + r) * 128 + c + 4];
        }
        __syncthreads();
#pragma unroll
        for (int kk = 0; kk < 16; kk++) {
            float4 b = *(float4*)&Ws[kk * 128 + 4 * tx];
#pragma unroll
            for (int i = 0; i < 8; i++) {
                float a = Xs[(8 * ty + i) * 16 + kk];
                acc[i][0] = fmaf(a, b.x, acc[i][0]);
                acc[i][1] = fmaf(a, b.y, acc[i][1]);
                acc[i][2] = fmaf(a, b.z, acc[i][2]);
                acc[i][3] = fmaf(a, b.w, acc[i][3]);
            }
        }
        __syncthreads();
    }
#pragma unroll
    for (int i = 0; i < 8; i++) {
        int row = r0 + 8 * ty + i;
        if (row < NN) {
            float s = g_dinv[row];
            float4 o = make_float4(acc[i][0] * s, acc[i][1] * s, acc[i][2] * s, acc[i][3] * s);
            *(float4*)&g_xw[row * 128 + 4 * tx] = o;
        }
    }
}

// ---------------- fused aggregation + BN + ReLU (+ pool for layer 2) ----------------
// one warp per dst node; register accumulation; single write per node
template <int LAYER>
__global__ void __launch_bounds__(256) k_agg_fused(const float* __restrict__ b,
                                                   const float* __restrict__ gam,
                                                   const float* __restrict__ bet,
                                                   const float* __restrict__ mu,
                                                   const float* __restrict__ var) {
    int warp = (blockIdx.x * blockDim.x + threadIdx.x) >> 5;
    int lane = threadIdx.x & 31;
    if (warp >= NN) return;
    int v = warp;
    int dd = lane * 4;
    int lo = g_doff[v], hi = g_doff[v + 1];

    // self-loop term + accumulate incoming messages (all pre-scaled by dinv[src])
    float4 a0 = *(const float4*)&g_xw[v * 128 + dd];
    float4 a1 = make_float4(0.f, 0.f, 0.f, 0.f);
    int e = lo;
    for (; e + 1 < hi; e += 2) {
        int s0 = __ldg(&g_ssorted[e]);
        int s1 = __ldg(&g_ssorted[e + 1]);
        float4 v0 = *(const float4*)&g_xw[s0 * 128 + dd];
        float4 v1 = *(const float4*)&g_xw[s1 * 128 + dd];
        a0.x += v0.x; a0.y += v0.y; a0.z += v0.z; a0.w += v0.w;
        a1.x += v1.x; a1.y += v1.y; a1.z += v1.z; a1.w += v1.w;
    }
    if (e < hi) {
        int s0 = __ldg(&g_ssorted[e]);
        float4 v0 = *(const float4*)&g_xw[s0 * 128 + dd];
        a0.x += v0.x; a0.y += v0.y; a0.z += v0.z; a0.w += v0.w;
    }
    float4 acc = make_float4(a0.x + a1.x, a0.y + a1.y, a0.z + a1.z, a0.w + a1.w);

    // BN constants for this thread's 4 channels
    float4 b4  = *(const float4*)&b[dd];
    float4 g4  = *(const float4*)&gam[dd];
    float4 t4  = *(const float4*)&bet[dd];
    float4 m4  = *(const float4*)&mu[dd];
    float4 v4  = *(const float4*)&var[dd];
    float s0c = g4.x * rsqrtf(v4.x + BN_EPS);
    float s1c = g4.y * rsqrtf(v4.y + BN_EPS);
    float s2c = g4.z * rsqrtf(v4.z + BN_EPS);
    float s3c = g4.w * rsqrtf(v4.w + BN_EPS);
    float c0 = (b4.x - m4.x) * s0c + t4.x;
    float c1 = (b4.y - m4.y) * s1c + t4.y;
    float c2 = (b4.z - m4.z) * s2c + t4.z;
    float c3 = (b4.w - m4.w) * s3c + t4.w;

    float din = g_dinv[v];
    float4 r;
    r.x = fmaxf(din * acc.x * s0c + c0, 0.f);
    r.y = fmaxf(din * acc.y * s1c + c1, 0.f);
    r.z = fmaxf(din * acc.z * s2c + c2, 0.f);
    r.w = fmaxf(din * acc.w * s3c + c3, 0.f);

    if (LAYER == 1) {
        *(float4*)&g_h[v * 128 + dd] = r;
    } else {
        int gr = g_nb32[v];
        red_add_v4(&g_gsum[gr * 128 + dd], r);
    }
}

// ---------------- edge encoder: per-graph register-accumulated relu(ea@We1+be1) ----------------
#define ECHUNKS 3
__global__ void __launch_bounds__(128) k_edge_enc(const float* __restrict__ EA,
                                                  const float* __restrict__ We1,
                                                  const float* __restrict__ be1) {
    int g = blockIdx.x;
    int lo = g_eoff[g], hi = g_eoff[g + 1];
    int cnt = hi - lo;
    int y = blockIdx.y;
    int cl = lo + (int)((long long)cnt * y / ECHUNKS);
    int ch = lo + (int)((long long)cnt * (y + 1) / ECHUNKS);
    int lane = threadIdx.x & 31;
    int w = threadIdx.x >> 5;

    float wr0[16], wr1[16], wr2[16], wr3[16];
#pragma unroll
    for (int k = 0; k < 16; k++) {
        wr0[k] = __ldg(&We1[k * 128 + lane]);
        wr1[k] = __ldg(&We1[k * 128 + 32 + lane]);
        wr2[k] = __ldg(&We1[k * 128 + 64 + lane]);
        wr3[k] = __ldg(&We1[k * 128 + 96 + lane]);
    }
    float br0 = __ldg(&be1[lane]);
    float br1 = __ldg(&be1[32 + lane]);
    float br2 = __ldg(&be1[64 + lane]);
    float br3 = __ldg(&be1[96 + lane]);
    float a0 = 0.f, a1 = 0.f, a2 = 0.f, a3 = 0.f;

    __shared__ __align__(16) float4 s_ea[128 * 4];
    for (int base = cl; base < ch; base += 128) {
        int n = min(128, ch - base);
        if ((int)threadIdx.x < n) {
            int e = g_eperm[base + threadIdx.x];
            const float4* p = (const float4*)&EA[(long long)e * 16];
            s_ea[threadIdx.x * 4 + 0] = __ldg(&p[0]);
            s_ea[threadIdx.x * 4 + 1] = __ldg(&p[1]);
            s_ea[threadIdx.x * 4 + 2] = __ldg(&p[2]);
            s_ea[threadIdx.x * 4 + 3] = __ldg(&p[3]);
        }
        __syncthreads();
        for (int j = w; j < n; j += 4) {
            float o0 = br0, o1 = br1, o2 = br2, o3 = br3;
#pragma unroll
            for (int q = 0; q < 4; q++) {
                float4 A = s_ea[j * 4 + q];
                float av[4] = {A.x, A.y, A.z, A.w};
#pragma unroll
                for (int kk = 0; kk < 4; kk++) {
                    int k = q * 4 + kk;
                    float aa = av[kk];
                    o0 = fmaf(aa, wr0[k], o0);
                    o1 = fmaf(aa, wr1[k], o1);
                    o2 = fmaf(aa, wr2[k], o2);
                    o3 = fmaf(aa, wr3[k], o3);
                }
            }
            a0 += fmaxf(o0, 0.f);
            a1 += fmaxf(o1, 0.f);
            a2 += fmaxf(o2, 0.f);
            a3 += fmaxf(o3, 0.f);
        }
        __syncthreads();
    }
    __shared__ float s_red[4][128];
    s_red[w][lane] = a0;
    s_red[w][32 + lane] = a1;
    s_red[w][64 + lane] = a2;
    s_red[w][96 + lane] = a3;
    __syncthreads();
    int t = threadIdx.x;
    float tot = s_red[0][t] + s_red[1][t] + s_red[2][t] + s_red[3][t];
    atomicAdd(&g_esum[g * 128 + t], tot);
}

// ---------------- final ----------------
__global__ void k_final(const float* __restrict__ We2, const float* __restrict__ be2,
                        float* __restrict__ out) {
    int g = blockIdx.x;
    int t = threadIdx.x;
    __shared__ float mh[128];
    int ec = g_ecnt[g];
    float inv = 1.0f / (float)max(ec, 1);
    mh[t] = g_esum[g * 128 + t] * inv;
    __syncthreads();
    float er = 0.f;
    if (ec > 0) {
#pragma unroll 8
        for (int k = 0; k < 128; k++)
            er = fmaf(mh[k], __ldg(&We2[k * 128 + t]), er);
        er += __ldg(&be2[t]);
    }
    float nc = (float)g_gcnt[g];
    float grp = g_gsum[g * 128 + t] / fmaxf(nc, 1.0f);
    out[g * 128 + t] = grp + er;
}

// ---------------- launch ----------------
extern "C" void kernel_launch(void* const* d_in, const int* in_sizes, int n_in,
                              void* d_out, int out_size) {
    const float* x     = (const float*)d_in[0];
    const void*  ei    = d_in[1];
    const void*  batch = d_in[2];
    const float* ea    = (const float*)d_in[3];
    int base = n_in - 16;
    const float* W1  = (const float*)d_in[base + 0];
    const float* b1  = (const float*)d_in[base + 1];
    const float* g1  = (const float*)d_in[base + 2];
    const float* bt1 = (const float*)d_in[base + 3];
    const float* m1  = (const float*)d_in[base + 4];
    const float* v1  = (const float*)d_in[base + 5];
    const float* W2  = (const float*)d_in[base + 6];
    const float* b2  = (const float*)d_in[base + 7];
    const float* g2  = (const float*)d_in[base + 8];
    const float* bt2 = (const float*)d_in[base + 9];
    const float* m2  = (const float*)d_in[base + 10];
    const float* v2  = (const float*)d_in[base + 11];
    const float* We1 = (const float*)d_in[base + 12];
    const float* be1 = (const float*)d_in[base + 13];
    const float* We2 = (const float*)d_in[base + 14];
    const float* be2 = (const float*)d_in[base + 15];
    float* out = (float*)d_out;

    k_detect<<<1, 256>>>((const int*)ei);
    k_init<<<512, 256>>>();
    k_edge_prep<<<2048, 256>>>(ei, batch);
    k_node_prep<<<512, 256>>>(batch);
    k_dinv<<<(NN + 255) / 256, 256>>>();
    k_scan_graph<<<1, GG>>>();
    k_scan_nodes<<<1, 1024>>>();
    k_escatter<<<2048, 256>>>();

    const int AGG_BLOCKS = (NN * 32 + 255) / 256;   // one warp per node
    // layer 1: GEMM -> fused agg+BN+ReLU -> g_h
    k_gemm_scale<<<(NN + 63) / 64, 256>>>(x, W1, 1);
    k_agg_fused<1><<<AGG_BLOCKS, 256>>>(b1, g1, bt1, m1, v1);

    // layer 2: GEMM -> fused agg+BN+ReLU+pool -> g_gsum (hidden never stored)
    k_gemm_scale<<<(NN + 63) / 64, 256>>>(x, W2, 2);
    k_agg_fused<2><<<AGG_BLOCKS, 256>>>(b2, g2, bt2, m2, v2);

    // edge encoder (bucketed by graph, register accumulation)
    {
        dim3 grid(GG, ECHUNKS);
        k_edge_enc<<<grid, 128>>>(ea, We1, be1);
    }

    k_final<<<GG, 128>>>(We2, be2, out);
}

// round 5
// speedup vs baseline: 1.2509x; 1.1276x over previous
#include <cuda_runtime.h>
#include <cstdint>

#define NN 100000
#define EE 1600000
#define DD 128
#define DEE 16
#define GG 512
#define BN_EPS 1e-5f

// ---------------- scratch (device globals; no allocation) ----------------
__device__ __align__(16) float g_xw[NN * DD];    // (X@W) * dinv[row], per layer
__device__ __align__(16) float g_h[NN * DD];     // layer1 output (post BN+ReLU)
__device__ float g_dinv[NN];
__device__ int   g_degi[NN];       // in-degree (edges only)
__device__ int   g_doff[NN + 1];   // CSR offsets by dst
__device__ int   g_dcur[NN];
__device__ int   g_src32[EE];
__device__ int   g_dst32[EE];
__device__ int   g_ssorted[EE];    // src ids sorted by dst
__device__ int   g_egr[EE];        // graph id per edge = batch[src]
__device__ int   g_eperm[EE];      // edge ids bucketed by graph
__device__ int   g_nb32[NN];       // batch id per node
__device__ int   g_ecnt[GG];
__device__ int   g_gcnt[GG];
__device__ int   g_eoff[GG + 1];
__device__ int   g_ecur[GG];
__device__ __align__(16) float g_gsum[GG * DD];
__device__ __align__(16) float g_esum[GG * DD];
__device__ int   g_is64;

__device__ __forceinline__ void red_add_v4(float* addr, float4 v) {
    asm volatile("red.global.add.v4.f32 [%0], {%1, %2, %3, %4};"
                 :: "l"(__cvta_generic_to_global(addr)),
                    "f"(v.x), "f"(v.y), "f"(v.z), "f"(v.w)
                 : "memory");
}
__device__ __forceinline__ int clampi(int v, int lo, int hi) {
    return min(max(v, lo), hi);
}

// ---------------- dtype probe ----------------
__global__ void k_detect(const int* __restrict__ ei_raw) {
    __shared__ int nz;
    if (threadIdx.x == 0) nz = 0;
    __syncthreads();
    for (int i = threadIdx.x; i < 1024; i += blockDim.x)
        if (ei_raw[2 * i + 1] != 0) nz = 1;
    __syncthreads();
    if (threadIdx.x == 0) g_is64 = (nz == 0) ? 1 : 0;
}

// ---------------- init (small buffers only) ----------------
__global__ void k_init() {
    int i = blockIdx.x * blockDim.x + threadIdx.x;
    int stride = gridDim.x * blockDim.x;
    for (int idx = i; idx < NN; idx += stride) {
        g_degi[idx] = 0;
        if (idx < GG * DD) { g_gsum[idx] = 0.f; g_esum[idx] = 0.f; }
        if (idx < GG) { g_ecnt[idx] = 0; g_gcnt[idx] = 0; }
    }
}

// ---------------- edge prep ----------------
__global__ void k_edge_prep(const void* __restrict__ ei_raw,
                            const void* __restrict__ batch_raw) {
    __shared__ int hist[GG];
    for (int t = threadIdx.x; t < GG; t += blockDim.x) hist[t] = 0;
    __syncthreads();
    const int is64 = g_is64;
    const int*       ei32 = (const int*)ei_raw;
    const long long* ei64 = (const long long*)ei_raw;
    const int*       bt32 = (const int*)batch_raw;
    const long long* bt64 = (const long long*)batch_raw;
    int i0 = blockIdx.x * blockDim.x + threadIdx.x;
    int stride = gridDim.x * blockDim.x;
    for (int e = i0; e < EE; e += stride) {
        int s, d;
        if (is64) { s = (int)ei64[e]; d = (int)ei64[EE + e]; }
        else      { s = ei32[e];      d = ei32[EE + e]; }
        s = clampi(s, 0, NN - 1);
        d = clampi(d, 0, NN - 1);
        g_src32[e] = s;
        g_dst32[e] = d;
        atomicAdd(&g_degi[d], 1);
        int gr = is64 ? (int)bt64[s] : bt32[s];
        gr = clampi(gr, 0, GG - 1);
        g_egr[e] = gr;
        atomicAdd(&hist[gr], 1);
    }
    __syncthreads();
    for (int t = threadIdx.x; t < GG; t += blockDim.x)
        if (hist[t]) atomicAdd(&g_ecnt[t], hist[t]);
}

// ---------------- node prep ----------------
__global__ void k_node_prep(const void* __restrict__ batch_raw) {
    __shared__ int hist[GG];
    for (int t = threadIdx.x; t < GG; t += blockDim.x) hist[t] = 0;
    __syncthreads();
    const int is64 = g_is64;
    const int*       bt32 = (const int*)batch_raw;
    const long long* bt64 = (const long long*)batch_raw;
    int i0 = blockIdx.x * blockDim.x + threadIdx.x;
    int stride = gridDim.x * blockDim.x;
    for (int v = i0; v < NN; v += stride) {
        int gr = is64 ? (int)bt64[v] : bt32[v];
        gr = clampi(gr, 0, GG - 1);
        g_nb32[v] = gr;
        atomicAdd(&hist[gr], 1);
    }
    __syncthreads();
    for (int t = threadIdx.x; t < GG; t += blockDim.x)
        if (hist[t]) atomicAdd(&g_gcnt[t], hist[t]);
}

// ---------------- per-graph edge scan (512, one block) ----------------
__global__ void k_scan_graph() {
    __shared__ int s[GG];
    int t = threadIdx.x;
    int v = g_ecnt[t];
    s[t] = v;
    __syncthreads();
    for (int off = 1; off < GG; off <<= 1) {
        int add = (t >= off) ? s[t - off] : 0;
        __syncthreads();
        s[t] += add;
        __syncthreads();
    }
    int excl = s[t] - v;
    g_eoff[t] = excl;
    g_ecur[t] = excl;
    if (t == GG - 1) g_eoff[GG] = s[t];
}

// ---------------- CSR-by-dst scan + dinv (100000, one block of 1024) ----------------
#define SCH 98   // 1024 * 98 = 100352 >= NN
__global__ void k_scan_nodes() {
    __shared__ int part[1024];
    int t = threadIdx.x;
    int base = t * SCH;
    int sum = 0;
    for (int i = 0; i < SCH; i++) {
        int idx = base + i;
        if (idx < NN) sum += g_degi[idx];
    }
    part[t] = sum;
    __syncthreads();
    for (int off = 1; off < 1024; off <<= 1) {
        int add = (t >= off) ? part[t - off] : 0;
        __syncthreads();
        part[t] += add;
        __syncthreads();
    }
    int run = part[t] - sum;   // exclusive prefix of this chunk
    for (int i = 0; i < SCH; i++) {
        int idx = base + i;
        if (idx < NN) {
            g_doff[idx] = run;
            g_dcur[idx] = run;
            int dg = g_degi[idx];
            g_dinv[idx] = rsqrtf((float)(dg + 1));
            run += dg;
        }
    }
    if (t == 1023) g_doff[NN] = EE;
}

// ---------------- scatter: sort srcs by dst (for agg) ----------------
__global__ void k_escatter_dst() {
    int i0 = blockIdx.x * blockDim.x + threadIdx.x;
    int stride = gridDim.x * blockDim.x;
    for (int e = i0; e < EE; e += stride) {
        int d = g_dst32[e];
        int q = atomicAdd(&g_dcur[d], 1);
        if (q < EE) g_ssorted[q] = g_src32[e];
    }
}

// ---------------- scatter: bucket edge ids by graph (for encoder) ----------------
__global__ void k_escatter_graph() {
    int i0 = blockIdx.x * blockDim.x + threadIdx.x;
    int stride = gridDim.x * blockDim.x;
    for (int e = i0; e < EE; e += stride) {
        int gr = g_egr[e];
        int p = atomicAdd(&g_ecur[gr], 1);
        if (p < EE) g_eperm[p] = e;
    }
}

// ---------------- GEMM: g_xw = (X @ W) * dinv[row], 64x128 tile ----------------
__global__ void __launch_bounds__(256) k_gemm_scale(const float* __restrict__ X,
                                                    const float* __restrict__ W,
                                                    int layer) {
    const float* __restrict__ Xp = (layer == 2) ? (const float*)g_h : X;
    __shared__ __align__(16) float Xs[64 * 16];
    __shared__ __align__(16) float Ws[16 * 128];
    int tid = threadIdx.x;
    int tx = tid & 31, ty = tid >> 5;
    int r0 = blockIdx.x * 64;
    float acc[8][4];
#pragma unroll
    for (int i = 0; i < 8; i++)
#pragma unroll
        for (int j = 0; j < 4; j++) acc[i][j] = 0.f;

    for (int k0 = 0; k0 < 128; k0 += 16) {
        {
            int i0 = tid * 4;
            int row = i0 >> 4, kk = i0 & 15;
            int gr = r0 + row;
            float4 v = make_float4(0.f, 0.f, 0.f, 0.f);
            if (gr < NN) v = *(const float4*)&Xp[gr * 128 + k0 + kk];
            *(float4*)&Xs[row * 16 + kk] = v;
        }
        {
            int i0 = tid * 8;
            int r = i0 >> 7, c = i0 & 127;
            *(float4*)&Ws[r * 128 + c]     = *(const float4*)&W[(k0 + r) * 128 + c];
            *(float4*)&Ws[r * 128 + c + 4] = *(const float4*)&W[(k0 + r) * 128 + c + 4];
        }
        __syncthreads();
#pragma unroll
        for (int kk = 0; kk < 16; kk++) {
            float4 b = *(float4*)&Ws[kk * 128 + 4 * tx];
#pragma unroll
            for (int i = 0; i < 8; i++) {
                float a = Xs[(8 * ty + i) * 16 + kk];
                acc[i][0] = fmaf(a, b.x, acc[i][0]);
                acc[i][1] = fmaf(a, b.y, acc[i][1]);
                acc[i][2] = fmaf(a, b.z, acc[i][2]);
                acc[i][3] = fmaf(a, b.w, acc[i][3]);
            }
        }
        __syncthreads();
    }
#pragma unroll
    for (int i = 0; i < 8; i++) {
        int row = r0 + 8 * ty + i;
        if (row < NN) {
            float s = g_dinv[row];
            float4 o = make_float4(acc[i][0] * s, acc[i][1] * s, acc[i][2] * s, acc[i][3] * s);
            *(float4*)&g_xw[row * 128 + 4 * tx] = o;
        }
    }
}

// ---------------- fused aggregation + BN + ReLU (+ pool for layer 2) ----------------
// one warp per dst node; register accumulation; single write per node
template <int LAYER>
__global__ void __launch_bounds__(256) k_agg_fused(const float* __restrict__ b,
                                                   const float* __restrict__ gam,
                                                   const float* __restrict__ bet,
                                                   const float* __restrict__ mu,
                                                   const float* __restrict__ var) {
    int warp = (blockIdx.x * blockDim.x + threadIdx.x) >> 5;
    int lane = threadIdx.x & 31;
    if (warp >= NN) return;
    int v = warp;
    int dd = lane * 4;
    int lo = g_doff[v], hi = g_doff[v + 1];

    // self-loop term + accumulate incoming messages (all pre-scaled by dinv[src])
    float4 a0 = *(const float4*)&g_xw[v * 128 + dd];
    float4 a1 = make_float4(0.f, 0.f, 0.f, 0.f);
    float4 a2 = make_float4(0.f, 0.f, 0.f, 0.f);
    float4 a3 = make_float4(0.f, 0.f, 0.f, 0.f);
    int e = lo;
    for (; e + 3 < hi; e += 4) {
        int s0 = __ldg(&g_ssorted[e]);
        int s1 = __ldg(&g_ssorted[e + 1]);
        int s2 = __ldg(&g_ssorted[e + 2]);
        int s3 = __ldg(&g_ssorted[e + 3]);
        float4 v0 = *(const float4*)&g_xw[s0 * 128 + dd];
        float4 v1 = *(const float4*)&g_xw[s1 * 128 + dd];
        float4 v2 = *(const float4*)&g_xw[s2 * 128 + dd];
        float4 v3 = *(const float4*)&g_xw[s3 * 128 + dd];
        a0.x += v0.x; a0.y += v0.y; a0.z += v0.z; a0.w += v0.w;
        a1.x += v1.x; a1.y += v1.y; a1.z += v1.z; a1.w += v1.w;
        a2.x += v2.x; a2.y += v2.y; a2.z += v2.z; a2.w += v2.w;
        a3.x += v3.x; a3.y += v3.y; a3.z += v3.z; a3.w += v3.w;
    }
    for (; e < hi; e++) {
        int s0 = __ldg(&g_ssorted[e]);
        float4 v0 = *(const float4*)&g_xw[s0 * 128 + dd];
        a0.x += v0.x; a0.y += v0.y; a0.z += v0.z; a0.w += v0.w;
    }
    float4 acc = make_float4(a0.x + a1.x + a2.x + a3.x,
                             a0.y + a1.y + a2.y + a3.y,
                             a0.z + a1.z + a2.z + a3.z,
                             a0.w + a1.w + a2.w + a3.w);

    // BN constants for this thread's 4 channels
    float4 b4  = *(const float4*)&b[dd];
    float4 g4  = *(const float4*)&gam[dd];
    float4 t4  = *(const float4*)&bet[dd];
    float4 m4  = *(const float4*)&mu[dd];
    float4 v4  = *(const float4*)&var[dd];
    float s0c = g4.x * rsqrtf(v4.x + BN_EPS);
    float s1c = g4.y * rsqrtf(v4.y + BN_EPS);
    float s2c = g4.z * rsqrtf(v4.z + BN_EPS);
    float s3c = g4.w * rsqrtf(v4.w + BN_EPS);
    float c0 = (b4.x - m4.x) * s0c + t4.x;
    float c1 = (b4.y - m4.y) * s1c + t4.y;
    float c2 = (b4.z - m4.z) * s2c + t4.z;
    float c3 = (b4.w - m4.w) * s3c + t4.w;

    float din = g_dinv[v];
    float4 r;
    r.x = fmaxf(din * acc.x * s0c + c0, 0.f);
    r.y = fmaxf(din * acc.y * s1c + c1, 0.f);
    r.z = fmaxf(din * acc.z * s2c + c2, 0.f);
    r.w = fmaxf(din * acc.w * s3c + c3, 0.f);

    if (LAYER == 1) {
        *(float4*)&g_h[v * 128 + dd] = r;
    } else {
        int gr = g_nb32[v];
        red_add_v4(&g_gsum[gr * 128 + dd], r);
    }
}

// ---------------- edge encoder: per-graph register-accumulated relu(ea@We1+be1) ----------------
#define ECHUNKS 3
__global__ void __launch_bounds__(128) k_edge_enc(const float* __restrict__ EA,
                                                  const float* __restrict__ We1,
                                                  const float* __restrict__ be1) {
    int g = blockIdx.x;
    int lo = g_eoff[g], hi = g_eoff[g + 1];
    int cnt = hi - lo;
    int y = blockIdx.y;
    int cl = lo + (int)((long long)cnt * y / ECHUNKS);
    int ch = lo + (int)((long long)cnt * (y + 1) / ECHUNKS);
    int lane = threadIdx.x & 31;
    int w = threadIdx.x >> 5;

    float wr0[16], wr1[16], wr2[16], wr3[16];
#pragma unroll
    for (int k = 0; k < 16; k++) {
        wr0[k] = __ldg(&We1[k * 128 + lane]);
        wr1[k] = __ldg(&We1[k * 128 + 32 + lane]);
        wr2[k] = __ldg(&We1[k * 128 + 64 + lane]);
        wr3[k] = __ldg(&We1[k * 128 + 96 + lane]);
    }
    float br0 = __ldg(&be1[lane]);
    float br1 = __ldg(&be1[32 + lane]);
    float br2 = __ldg(&be1[64 + lane]);
    float br3 = __ldg(&be1[96 + lane]);
    float a0 = 0.f, a1 = 0.f, a2 = 0.f, a3 = 0.f;

    __shared__ __align__(16) float4 s_ea[128 * 4];
    for (int base = cl; base < ch; base += 128) {
        int n = min(128, ch - base);
        if ((int)threadIdx.x < n) {
            int e = g_eperm[base + threadIdx.x];
            const float4* p = (const float4*)&EA[(long long)e * 16];
            s_ea[threadIdx.x * 4 + 0] = __ldg(&p[0]);
            s_ea[threadIdx.x * 4 + 1] = __ldg(&p[1]);
            s_ea[threadIdx.x * 4 + 2] = __ldg(&p[2]);
            s_ea[threadIdx.x * 4 + 3] = __ldg(&p[3]);
        }
        __syncthreads();
        for (int j = w; j < n; j += 4) {
            float o0 = br0, o1 = br1, o2 = br2, o3 = br3;
#pragma unroll
            for (int q = 0; q < 4; q++) {
                float4 A = s_ea[j * 4 + q];
                float av[4] = {A.x, A.y, A.z, A.w};
#pragma unroll
                for (int kk = 0; kk < 4; kk++) {
                    int k = q * 4 + kk;
                    float aa = av[kk];
                    o0 = fmaf(aa, wr0[k], o0);
                    o1 = fmaf(aa, wr1[k], o1);
                    o2 = fmaf(aa, wr2[k], o2);
                    o3 = fmaf(aa, wr3[k], o3);
                }
            }
            a0 += fmaxf(o0, 0.f);
            a1 += fmaxf(o1, 0.f);
            a2 += fmaxf(o2, 0.f);
            a3 += fmaxf(o3, 0.f);
        }
        __syncthreads();
    }
    __shared__ float s_red[4][128];
    s_red[w][lane] = a0;
    s_red[w][32 + lane] = a1;
    s_red[w][64 + lane] = a2;
    s_red[w][96 + lane] = a3;
    __syncthreads();
    int t = threadIdx.x;
    float tot = s_red[0][t] + s_red[1][t] + s_red[2][t] + s_red[3][t];
    atomicAdd(&g_esum[g * 128 + t], tot);
}

// ---------------- final ----------------
__global__ void k_final(const float* __restrict__ We2, const float* __restrict__ be2,
                        float* __restrict__ out) {
    int g = blockIdx.x;
    int t = threadIdx.x;
    __shared__ float mh[128];
    int ec = g_ecnt[g];
    float inv = 1.0f / (float)max(ec, 1);
    mh[t] = g_esum[g * 128 + t] * inv;
    __syncthreads();
    float er = 0.f;
    if (ec > 0) {
#pragma unroll 8
        for (int k = 0; k < 128; k++)
            er = fmaf(mh[k], __ldg(&We2[k * 128 + t]), er);
        er += __ldg(&be2[t]);
    }
    float nc = (float)g_gcnt[g];
    float grp = g_gsum[g * 128 + t] / fmaxf(nc, 1.0f);
    out[g * 128 + t] = grp + er;
}

// ---------------- launch ----------------
extern "C" void kernel_launch(void* const* d_in, const int* in_sizes, int n_in,
                              void* d_out, int out_size) {
    const float* x     = (const float*)d_in[0];
    const void*  ei    = d_in[1];
    const void*  batch = d_in[2];
    const float* ea    = (const float*)d_in[3];
    int base = n_in - 16;
    const float* W1  = (const float*)d_in[base + 0];
    const float* b1  = (const float*)d_in[base + 1];
    const float* g1  = (const float*)d_in[base + 2];
    const float* bt1 = (const float*)d_in[base + 3];
    const float* m1  = (const float*)d_in[base + 4];
    const float* v1  = (const float*)d_in[base + 5];
    const float* W2  = (const float*)d_in[base + 6];
    const float* b2  = (const float*)d_in[base + 7];
    const float* g2  = (const float*)d_in[base + 8];
    const float* bt2 = (const float*)d_in[base + 9];
    const float* m2  = (const float*)d_in[base + 10];
    const float* v2  = (const float*)d_in[base + 11];
    const float* We1 = (const float*)d_in[base + 12];
    const float* be1 = (const float*)d_in[base + 13];
    const float* We2 = (const float*)d_in[base + 14];
    const float* be2 = (const float*)d_in[base + 15];
    float* out = (float*)d_out;

    // Streams/events created once, on the first (non-captured) correctness call.
    // Same launch structure every call -> deterministic; capture sees identical graphs.
    static cudaStream_t sEnc = 0, sSort = 0;
    static cudaEvent_t evPrep = 0, evNodes = 0, evSorted = 0, evEnc = 0;
    if (sEnc == 0) {
        cudaStreamCreateWithFlags(&sEnc, cudaStreamNonBlocking);
        cudaStreamCreateWithFlags(&sSort, cudaStreamNonBlocking);
        cudaEventCreateWithFlags(&evPrep,   cudaEventDisableTiming);
        cudaEventCreateWithFlags(&evNodes,  cudaEventDisableTiming);
        cudaEventCreateWithFlags(&evSorted, cudaEventDisableTiming);
        cudaEventCreateWithFlags(&evEnc,    cudaEventDisableTiming);
    }

    // ---- main stream: prep ----
    k_detect<<<1, 256>>>((const int*)ei);
    k_init<<<512, 256>>>();
    k_edge_prep<<<2048, 256>>>(ei, batch);

    // ---- fork encoder chain (needs only g_egr/g_ecnt/g_esum from above) ----
    cudaEventRecord(evPrep, 0);
    cudaStreamWaitEvent(sEnc, evPrep, 0);
    k_scan_graph<<<1, GG, 0, sEnc>>>();
    k_escatter_graph<<<2048, 256, 0, sEnc>>>();
    {
        dim3 grid(GG, ECHUNKS);
        k_edge_enc<<<grid, 128, 0, sEnc>>>(ea, We1, be1);
    }
    cudaEventRecord(evEnc, sEnc);

    // ---- main stream continues GCN chain ----
    k_node_prep<<<512, 256>>>(batch);
    k_scan_nodes<<<1, 1024>>>();

    // fork dst-sort to overlap with GEMM1
    cudaEventRecord(evNodes, 0);
    cudaStreamWaitEvent(sSort, evNodes, 0);
    k_escatter_dst<<<2048, 256, 0, sSort>>>();
    cudaEventRecord(evSorted, sSort);

    const int AGG_BLOCKS = (NN * 32 + 255) / 256;   // one warp per node
    // layer 1: GEMM -> fused agg+BN+ReLU -> g_h
    k_gemm_scale<<<(NN + 63) / 64, 256>>>(x, W1, 1);
    cudaStreamWaitEvent(0, evSorted, 0);
    k_agg_fused<1><<<AGG_BLOCKS, 256>>>(b1, g1, bt1, m1, v1);

    // layer 2: GEMM -> fused agg+BN+ReLU+pool -> g_gsum (hidden never stored)
    k_gemm_scale<<<(NN + 63) / 64, 256>>>(x, W2, 2);
    k_agg_fused<2><<<AGG_BLOCKS, 256>>>(b2, g2, bt2, m2, v2);

    // ---- join encoder chain, finalize ----
    cudaStreamWaitEvent(0, evEnc, 0);
    k_final<<<GG, 128>>>(We2, be2, out);
}